// round 2
// baseline (speedup 1.0000x reference)
#include <cuda_runtime.h>
#include <cstddef>

#define N_USER  100000
#define N_MOVIE 20000
#define D_IN    64
#define HID     128
#define OUT_D   64
#define NE      600000

// ---------------------------------------------------------------------------
// Scratch: one big zero-init __device__ array (allocation-free scratch).
// Layout (float offsets):
//   agg1   [N_USER  * 64 ] = 6,400,000   (conv1 aggregation: movie->user)
//   agg2   [N_MOVIE * 64 ] = 1,280,000   (conv2 aggregation: user->movie)
//   agg3   [N_USER  * 128] = 12,800,000  (conv3 aggregation: movie_x->user)
//   degU   [N_USER]        = 100,000
//   degM   [N_MOVIE]       = 20,000
//   ---- zero region ends: 20,600,000 floats ----
//   userx  [N_USER  * 128] = 12,800,000  (conv1 output)
//   moviex [N_MOVIE * 128] = 2,560,000   (conv2 output)
// ---------------------------------------------------------------------------
#define OFF_AGG1   0
#define OFF_AGG2   6400000
#define OFF_AGG3   7680000
#define OFF_DEGU   20480000
#define OFF_DEGM   20580000
#define ZERO_FLOATS 20600000
#define OFF_USERX  20600000
#define OFF_MOVIEX 33400000
#define SCRATCH_TOTAL 35960000

__device__ float g_scratch[SCRATCH_TOTAL];

// ---------------------------------------------------------------------------
// Vector reduction: red.global.add.v4.f32 (sm_90+). No-return L2-side atomic.
// ---------------------------------------------------------------------------
__device__ __forceinline__ void red_add_v4(float* p, float4 v) {
    asm volatile("red.global.add.v4.f32 [%0], {%1, %2, %3, %4};"
                 :: "l"(p), "f"(v.x), "f"(v.y), "f"(v.z), "f"(v.w)
                 : "memory");
}

// ---------------------------------------------------------------------------
// Fused conv1+conv2 scatter (both are 64-wide, same edge list):
//   per (edge e, chunk c):  s = edge_movie[e], d = edge_user[e]
//     agg1[d] += x_movie[s]   (conv1: movie -> user)
//     agg2[s] += x_user[d]    (conv2: user -> movie)
//   chunk 0 also bumps both degree counters.
// 16 chunks of float4 per 64-float row.
// ---------------------------------------------------------------------------
__global__ __launch_bounds__(256)
void scatter12_kernel(const float4* __restrict__ x_movie,
                      const float4* __restrict__ x_user,
                      const int* __restrict__ edge_movie,
                      const int* __restrict__ edge_user,
                      float* __restrict__ agg1,
                      float* __restrict__ agg2,
                      float* __restrict__ degU,
                      float* __restrict__ degM)
{
    int t = blockIdx.x * 256 + threadIdx.x;
    int e = t >> 4;
    if (e >= NE) return;
    int c = t & 15;
    int s = __ldg(&edge_movie[e]);   // movie
    int d = __ldg(&edge_user[e]);    // user
    float4 vm = __ldg(&x_movie[s * 16 + c]);
    red_add_v4(agg1 + (d * 16 + c) * 4, vm);
    float4 vu = __ldg(&x_user[d * 16 + c]);
    red_add_v4(agg2 + (s * 16 + c) * 4, vu);
    if (c == 0) {
        atomicAdd(degU + d, 1.0f);
        atomicAdd(degM + s, 1.0f);
    }
}

// ---------------------------------------------------------------------------
// Conv3 scatter: moviex (128-wide) -> agg3 (user). 32 chunks per row.
// ---------------------------------------------------------------------------
__global__ __launch_bounds__(256)
void scatter3_kernel(const float4* __restrict__ xsrc,
                     const int* __restrict__ edge_movie,
                     const int* __restrict__ edge_user,
                     float* __restrict__ agg3)
{
    int t = blockIdx.x * 256 + threadIdx.x;
    int e = t >> 5;
    if (e >= NE) return;
    int c = t & 31;
    int s = __ldg(&edge_movie[e]);
    int d = __ldg(&edge_user[e]);
    float4 v = __ldg(&xsrc[s * 32 + c]);
    red_add_v4(agg3 + (d * 32 + c) * 4, v);
}

// ---------------------------------------------------------------------------
// Node-update kernel:
//   h = relu( (agg/deg) @ Wl + x @ Wr + bias )        [row-tile GEMM, K'=2K]
//   optionally: hidOut = h
//   optionally (FUSE): linOut = h @ Wlin + blin       [second GEMM from SMEM]
// Block = 256 threads, TM = 32 rows/tile (row counts divide exactly).
// ---------------------------------------------------------------------------
template<int K, bool FUSE, bool WRITE_HID>
__global__ __launch_bounds__(256)
void update_kernel(const float* __restrict__ agg,
                   const float* __restrict__ deg,
                   const float* __restrict__ x,
                   const float* __restrict__ Wl,
                   const float* __restrict__ Wr,
                   const float* __restrict__ bias,
                   const float* __restrict__ Wlin,
                   const float* __restrict__ blin,
                   float* __restrict__ hidOut,
                   float* __restrict__ linOut)
{
    constexpr int TM = 32;
    constexpr int K2 = 2 * K;
    extern __shared__ float smem[];
    float* sW    = smem;                       // [K2][128]
    float* sIn   = sW + K2 * HID;              // [TM][K2]
    float* sH    = sIn + TM * K2;              // [TM][128]  (FUSE only)
    float* sWlin = sH + (FUSE ? TM * HID : 0); // [128][64]  (FUSE only)

    const int tid = threadIdx.x;
    const int rowBase = blockIdx.x * TM;

    // --- load weights (concatenated along K): sW[0..K) = Wl, sW[K..2K) = Wr
    {
        const float4* Wl4 = (const float4*)Wl;
        const float4* Wr4 = (const float4*)Wr;
        float4* sW4 = (float4*)sW;
        const int nv = K * (HID / 4);
        for (int i = tid; i < nv; i += 256) sW4[i]      = Wl4[i];
        for (int i = tid; i < nv; i += 256) sW4[nv + i] = Wr4[i];
    }
    if (FUSE) {
        const float4* Wlin4 = (const float4*)Wlin;
        float4* sWlin4 = (float4*)sWlin;
        for (int i = tid; i < HID * (OUT_D / 4); i += 256) sWlin4[i] = Wlin4[i];
    }
    // --- load inputs: sIn[r][0..K) = agg_row/deg, sIn[r][K..2K) = x_row
    {
        constexpr int VR = K / 4;
        const float4* agg4 = (const float4*)agg;
        const float4* x4   = (const float4*)x;
        for (int i = tid; i < TM * VR; i += 256) {
            int r = i / VR, j = i % VR;
            int row = rowBase + r;
            float inv = 1.0f / fmaxf(__ldg(&deg[row]), 1.0f);
            float4 a = agg4[(size_t)row * VR + j];
            a.x *= inv; a.y *= inv; a.z *= inv; a.w *= inv;
            float4 xv = x4[(size_t)row * VR + j];
            float4* sRow = (float4*)(sIn + r * K2);
            sRow[j]      = a;
            sRow[VR + j] = xv;
        }
    }
    __syncthreads();

    // --- GEMM1: [TM x K2] @ [K2 x 128]
    const int rg = tid >> 4;   // 0..15
    const int cg = tid & 15;   // 0..15
    float acc0[8], acc1[8];
    #pragma unroll
    for (int j = 0; j < 8; j++) { acc0[j] = 0.f; acc1[j] = 0.f; }

    const float4* in04 = (const float4*)(sIn + (2 * rg) * K2);
    const float4* in14 = (const float4*)(sIn + (2 * rg + 1) * K2);
    const float* wp = sW + cg * 8;

    #pragma unroll 2
    for (int k4 = 0; k4 < K2 / 4; k4++) {
        float4 av = in04[k4];
        float4 bv = in14[k4];
        float a0s[4] = {av.x, av.y, av.z, av.w};
        float a1s[4] = {bv.x, bv.y, bv.z, bv.w};
        #pragma unroll
        for (int u = 0; u < 4; u++) {
            int kk = k4 * 4 + u;
            const float4* wrow = (const float4*)(wp + kk * HID);
            float4 w0 = wrow[0];
            float4 w1 = wrow[1];
            float w[8] = {w0.x, w0.y, w0.z, w0.w, w1.x, w1.y, w1.z, w1.w};
            float a0 = a0s[u], a1 = a1s[u];
            #pragma unroll
            for (int j = 0; j < 8; j++) {
                acc0[j] = fmaf(a0, w[j], acc0[j]);
                acc1[j] = fmaf(a1, w[j], acc1[j]);
            }
        }
    }

    // bias + relu
    const float* bp = bias + cg * 8;
    #pragma unroll
    for (int j = 0; j < 8; j++) {
        float bj = __ldg(bp + j);
        acc0[j] = fmaxf(acc0[j] + bj, 0.f);
        acc1[j] = fmaxf(acc1[j] + bj, 0.f);
    }

    const int row0 = rowBase + 2 * rg;
    if (WRITE_HID) {
        float* h0 = hidOut + (size_t)row0 * HID + cg * 8;
        ((float4*)h0)[0] = make_float4(acc0[0], acc0[1], acc0[2], acc0[3]);
        ((float4*)h0)[1] = make_float4(acc0[4], acc0[5], acc0[6], acc0[7]);
        float* h1 = h0 + HID;
        ((float4*)h1)[0] = make_float4(acc1[0], acc1[1], acc1[2], acc1[3]);
        ((float4*)h1)[1] = make_float4(acc1[4], acc1[5], acc1[6], acc1[7]);
    }

    if (FUSE) {
        float* s0 = sH + (2 * rg) * HID + cg * 8;
        ((float4*)s0)[0] = make_float4(acc0[0], acc0[1], acc0[2], acc0[3]);
        ((float4*)s0)[1] = make_float4(acc0[4], acc0[5], acc0[6], acc0[7]);
        float* s1 = s0 + HID;
        ((float4*)s1)[0] = make_float4(acc1[0], acc1[1], acc1[2], acc1[3]);
        ((float4*)s1)[1] = make_float4(acc1[4], acc1[5], acc1[6], acc1[7]);
        __syncthreads();

        // --- GEMM2: [TM x 128] @ [128 x 64] + blin
        const int r  = tid >> 3;  // 0..31
        const int c2 = tid & 7;   // 0..7
        float acc[8];
        #pragma unroll
        for (int j = 0; j < 8; j++) acc[j] = 0.f;
        const float* hp  = sH + r * HID;
        const float* wp2 = sWlin + c2 * 8;
        #pragma unroll 4
        for (int k = 0; k < HID; k++) {
            const float4* wrow = (const float4*)(wp2 + k * OUT_D);
            float4 w0 = wrow[0];
            float4 w1 = wrow[1];
            float w[8] = {w0.x, w0.y, w0.z, w0.w, w1.x, w1.y, w1.z, w1.w};
            float h = hp[k];
            #pragma unroll
            for (int j = 0; j < 8; j++) acc[j] = fmaf(h, w[j], acc[j]);
        }
        const float* blp = blin + c2 * 8;
        #pragma unroll
        for (int j = 0; j < 8; j++) acc[j] += __ldg(blp + j);
        float* op = linOut + (size_t)(rowBase + r) * OUT_D + c2 * 8;
        ((float4*)op)[0] = make_float4(acc[0], acc[1], acc[2], acc[3]);
        ((float4*)op)[1] = make_float4(acc[4], acc[5], acc[6], acc[7]);
    }
}

// ---------------------------------------------------------------------------
// Host launcher
// ---------------------------------------------------------------------------
extern "C" void kernel_launch(void* const* d_in, const int* in_sizes, int n_in,
                              void* d_out, int out_size)
{
    const float* x_user    = (const float*)d_in[0];
    const float* x_movie   = (const float*)d_in[1];
    const int*   edge_user = (const int*)d_in[2];
    const int*   edge_movie= (const int*)d_in[3];
    const float* W1l = (const float*)d_in[4];
    const float* W1r = (const float*)d_in[5];
    const float* b1  = (const float*)d_in[6];
    const float* W2l = (const float*)d_in[7];
    const float* W2r = (const float*)d_in[8];
    const float* b2  = (const float*)d_in[9];
    const float* W3l = (const float*)d_in[10];
    const float* W3r = (const float*)d_in[11];
    const float* b3  = (const float*)d_in[12];
    const float* Wlin1 = (const float*)d_in[13];
    const float* blin1 = (const float*)d_in[14];
    const float* Wlin2 = (const float*)d_in[15];
    const float* blin2 = (const float*)d_in[16];

    float* out = (float*)d_out;
    float* out_user  = out;
    float* out_movie = out + (size_t)N_USER * OUT_D;

    float* scratch = nullptr;
    cudaGetSymbolAddress((void**)&scratch, g_scratch);
    float* agg1   = scratch + OFF_AGG1;
    float* agg2   = scratch + OFF_AGG2;
    float* agg3   = scratch + OFF_AGG3;
    float* degU   = scratch + OFF_DEGU;
    float* degM   = scratch + OFF_DEGM;
    float* userx  = scratch + OFF_USERX;
    float* moviex = scratch + OFF_MOVIEX;

    // dynamic smem sizes (bytes)
    const int SM_K64   = (2*64*HID + 32*2*64) * 4;                        // 81920
    const int SM_K64F  = (2*64*HID + 32*2*64 + 32*HID + HID*OUT_D) * 4;   // 131072
    const int SM_K128F = (2*128*HID + 32*2*128 + 32*HID + HID*OUT_D) * 4; // 212992

    cudaFuncSetAttribute(update_kernel<64, false, true>,
                         cudaFuncAttributeMaxDynamicSharedMemorySize, SM_K64);
    cudaFuncSetAttribute(update_kernel<64, true, true>,
                         cudaFuncAttributeMaxDynamicSharedMemorySize, SM_K64F);
    cudaFuncSetAttribute(update_kernel<128, true, false>,
                         cudaFuncAttributeMaxDynamicSharedMemorySize, SM_K128F);

    // zero aggregation + degree buffers
    cudaMemsetAsync(scratch, 0, (size_t)ZERO_FLOATS * sizeof(float), 0);

    // fused conv1+conv2 scatter (64-wide each) + degree counters
    scatter12_kernel<<<(NE * 16) / 256, 256>>>(
        (const float4*)x_movie, (const float4*)x_user,
        edge_movie, edge_user, agg1, agg2, degU, degM);

    // conv2 update (movie): writes moviex and fused out_movie
    update_kernel<64, true, true><<<N_MOVIE / 32, 256, SM_K64F>>>(
        agg2, degM, x_movie, W2l, W2r, b2, Wlin2, blin2, moviex, out_movie);

    // conv1 update (user): writes userx
    update_kernel<64, false, true><<<N_USER / 32, 256, SM_K64>>>(
        agg1, degU, x_user, W1l, W1r, b1, nullptr, nullptr, userx, nullptr);

    // conv3 scatter: moviex (128-wide) -> user agg3
    scatter3_kernel<<<(NE * 32) / 256, 256>>>(
        (const float4*)moviex, edge_movie, edge_user, agg3);

    // conv3 update (user) + fused lin1: writes out_user
    update_kernel<128, true, false><<<N_USER / 32, 256, SM_K128F>>>(
        agg3, degU, userx, W3l, W3r, b3, Wlin1, blin1, nullptr, out_user);
}

// round 3
// speedup vs baseline: 1.7604x; 1.7604x over previous
#include <cuda_runtime.h>
#include <cstddef>

#define N_USER  100000
#define N_MOVIE 20000
#define D_IN    64
#define HID     128
#define OUT_D   64
#define NE      600000

// ---------------------------------------------------------------------------
// Scratch (zero-init __device__ array). Float offsets:
//   agg1 [N_USER*64], agg2 [N_MOVIE*64], agg3 [N_USER*128],
//   degU [N_USER], degM [N_MOVIE]  <- zeroed each call
//   userx [N_USER*128], moviex [N_MOVIE*128]
// ---------------------------------------------------------------------------
#define OFF_AGG1   0
#define OFF_AGG2   6400000
#define OFF_AGG3   7680000
#define OFF_DEGU   20480000
#define OFF_DEGM   20580000
#define ZERO_FLOATS 20600000
#define OFF_USERX  20600000
#define OFF_MOVIEX 33400000
#define SCRATCH_TOTAL 35960000

__device__ float g_scratch[SCRATCH_TOTAL];

__device__ __forceinline__ void red_add_v4(float* p, float4 v) {
    asm volatile("red.global.add.v4.f32 [%0], {%1, %2, %3, %4};"
                 :: "l"(p), "f"(v.x), "f"(v.y), "f"(v.z), "f"(v.w)
                 : "memory");
}

// ---------------------------------------------------------------------------
// Fused conv1+conv2 scatter (both 64-wide, same edge list).
// ---------------------------------------------------------------------------
__global__ __launch_bounds__(256)
void scatter12_kernel(const float4* __restrict__ x_movie,
                      const float4* __restrict__ x_user,
                      const int* __restrict__ edge_movie,
                      const int* __restrict__ edge_user,
                      float* __restrict__ agg1,
                      float* __restrict__ agg2,
                      float* __restrict__ degU,
                      float* __restrict__ degM)
{
    int t = blockIdx.x * 256 + threadIdx.x;
    int e = t >> 4;
    if (e >= NE) return;
    int c = t & 15;
    int s = __ldg(&edge_movie[e]);   // movie
    int d = __ldg(&edge_user[e]);    // user
    float4 vm = __ldg(&x_movie[s * 16 + c]);
    red_add_v4(agg1 + (d * 16 + c) * 4, vm);
    float4 vu = __ldg(&x_user[d * 16 + c]);
    red_add_v4(agg2 + (s * 16 + c) * 4, vu);
    if (c == 0) {
        atomicAdd(degU + d, 1.0f);
        atomicAdd(degM + s, 1.0f);
    }
}

// ---------------------------------------------------------------------------
// Conv3 scatter: moviex (128-wide) -> agg3 (user).
// ---------------------------------------------------------------------------
__global__ __launch_bounds__(256)
void scatter3_kernel(const float4* __restrict__ xsrc,
                     const int* __restrict__ edge_movie,
                     const int* __restrict__ edge_user,
                     float* __restrict__ agg3)
{
    int t = blockIdx.x * 256 + threadIdx.x;
    int e = t >> 5;
    if (e >= NE) return;
    int c = t & 31;
    int s = __ldg(&edge_movie[e]);
    int d = __ldg(&edge_user[e]);
    float4 v = __ldg(&xsrc[s * 32 + c]);
    red_add_v4(agg3 + (d * 32 + c) * 4, v);
}

// ---------------------------------------------------------------------------
// Node-update: h = relu((agg/deg)@Wl + x@Wr + b); optional hidOut=h;
// optional FUSE: linOut = h@Wlin + blin.
// TM=64 rows/block, 256 threads. GEMM1 thread tile: 4 rows x 8 cols
// (rg=tid/16 -> rows rg*4..+3; cg=tid%16 -> cols cg*8..+7).
// GEMM2 thread tile: 4 rows x 4 cols. sH overlays sIn after GEMM1.
// ---------------------------------------------------------------------------
template<int K, bool FUSE, bool WRITE_HID>
__global__ __launch_bounds__(256)
void update_kernel(const float* __restrict__ agg,
                   const float* __restrict__ deg,
                   const float* __restrict__ x,
                   const float* __restrict__ Wl,
                   const float* __restrict__ Wr,
                   const float* __restrict__ bias,
                   const float* __restrict__ Wlin,
                   const float* __restrict__ blin,
                   float* __restrict__ hidOut,
                   float* __restrict__ linOut,
                   int nRows)
{
    constexpr int TM = 64;
    constexpr int K2 = 2 * K;
    constexpr int VR = K / 4;     // float4 per half input row
    constexpr int VK2 = K2 / 4;   // float4 per full input row
    extern __shared__ float smem[];
    float* sW    = smem;                 // [K2][HID]
    float* sIn   = sW + K2 * HID;        // [TM][K2], reused as sH [TM][HID]
    float* sWlin = sIn + TM * K2;        // [HID][OUT_D] (FUSE only)
    float* sH    = sIn;                  // overlay

    const int tid = threadIdx.x;
    const int rowBase = blockIdx.x * TM;
    int nValid = nRows - rowBase;
    if (nValid > TM) nValid = TM;

    // --- stage weights: sW[0..K) = Wl, sW[K..2K) = Wr
    {
        const float4* Wl4 = (const float4*)Wl;
        const float4* Wr4 = (const float4*)Wr;
        float4* sW4 = (float4*)sW;
        const int nv = K * (HID / 4);
        for (int i = tid; i < nv; i += 256) { sW4[i] = Wl4[i]; sW4[nv + i] = Wr4[i]; }
    }
    if (FUSE) {
        const float4* Wlin4 = (const float4*)Wlin;
        float4* s4 = (float4*)sWlin;
        for (int i = tid; i < HID * (OUT_D / 4); i += 256) s4[i] = Wlin4[i];
    }
    // --- stage inputs: sIn[r][0..K)=agg/deg, sIn[r][K..2K)=x
    {
        const float4* agg4 = (const float4*)agg;
        const float4* x4   = (const float4*)x;
        for (int i = tid; i < TM * VR; i += 256) {
            int r = i / VR, j = i % VR;
            int row = rowBase + r;
            float4 a, xv;
            if (r < nValid) {
                float inv = 1.0f / fmaxf(__ldg(&deg[row]), 1.0f);
                a = agg4[(size_t)row * VR + j];
                a.x *= inv; a.y *= inv; a.z *= inv; a.w *= inv;
                xv = x4[(size_t)row * VR + j];
            } else {
                a = make_float4(0.f, 0.f, 0.f, 0.f); xv = a;
            }
            float4* sRow = (float4*)(sIn + r * K2);
            sRow[j]      = a;
            sRow[VR + j] = xv;
        }
    }
    __syncthreads();

    // --- GEMM1: [TM x K2] @ [K2 x HID], 4x8 per thread
    const int rg = tid >> 4;   // 0..15
    const int cg = tid & 15;   // 0..15
    float acc[4][8];
    #pragma unroll
    for (int r = 0; r < 4; r++)
        #pragma unroll
        for (int j = 0; j < 8; j++) acc[r][j] = 0.f;

    const float* wp = sW + cg * 8;
    const float4* in4[4];
    #pragma unroll
    for (int r = 0; r < 4; r++) in4[r] = (const float4*)(sIn + (rg * 4 + r) * K2);

    #pragma unroll 2
    for (int k4 = 0; k4 < VK2; k4++) {
        float4 av[4];
        #pragma unroll
        for (int r = 0; r < 4; r++) av[r] = in4[r][k4];
        float as[4][4];
        #pragma unroll
        for (int r = 0; r < 4; r++) {
            as[r][0] = av[r].x; as[r][1] = av[r].y; as[r][2] = av[r].z; as[r][3] = av[r].w;
        }
        #pragma unroll
        for (int u = 0; u < 4; u++) {
            const float4* wrow = (const float4*)(wp + (k4 * 4 + u) * HID);
            float4 w0 = wrow[0];
            float4 w1 = wrow[1];
            float w[8] = {w0.x, w0.y, w0.z, w0.w, w1.x, w1.y, w1.z, w1.w};
            #pragma unroll
            for (int r = 0; r < 4; r++) {
                float a = as[r][u];
                #pragma unroll
                for (int j = 0; j < 8; j++) acc[r][j] = fmaf(a, w[j], acc[r][j]);
            }
        }
    }

    // bias + relu
    {
        const float* bp = bias + cg * 8;
        float bj[8];
        #pragma unroll
        for (int j = 0; j < 8; j++) bj[j] = __ldg(bp + j);
        #pragma unroll
        for (int r = 0; r < 4; r++)
            #pragma unroll
            for (int j = 0; j < 8; j++) acc[r][j] = fmaxf(acc[r][j] + bj[j], 0.f);
    }

    if (WRITE_HID) {
        #pragma unroll
        for (int r = 0; r < 4; r++) {
            int row = rowBase + rg * 4 + r;
            if (rg * 4 + r < nValid) {
                float* h = hidOut + (size_t)row * HID + cg * 8;
                ((float4*)h)[0] = make_float4(acc[r][0], acc[r][1], acc[r][2], acc[r][3]);
                ((float4*)h)[1] = make_float4(acc[r][4], acc[r][5], acc[r][6], acc[r][7]);
            }
        }
    }

    if (FUSE) {
        __syncthreads();   // all GEMM1 reads of sIn done before overlay write
        #pragma unroll
        for (int r = 0; r < 4; r++) {
            float* s = sH + (rg * 4 + r) * HID + cg * 8;
            ((float4*)s)[0] = make_float4(acc[r][0], acc[r][1], acc[r][2], acc[r][3]);
            ((float4*)s)[1] = make_float4(acc[r][4], acc[r][5], acc[r][6], acc[r][7]);
        }
        __syncthreads();

        // --- GEMM2: [TM x HID] @ [HID x OUT_D], 4x4 per thread
        const int rg2 = tid >> 4;  // rows rg2*4..+3
        const int cg2 = tid & 15;  // cols cg2*4..+3
        float a2[4][4];
        #pragma unroll
        for (int r = 0; r < 4; r++)
            #pragma unroll
            for (int c = 0; c < 4; c++) a2[r][c] = 0.f;

        const float4* h4[4];
        #pragma unroll
        for (int r = 0; r < 4; r++) h4[r] = (const float4*)(sH + (rg2 * 4 + r) * HID);
        const float* wl2 = sWlin + cg2 * 4;

        #pragma unroll 2
        for (int k4 = 0; k4 < HID / 4; k4++) {
            float4 hv[4];
            #pragma unroll
            for (int r = 0; r < 4; r++) hv[r] = h4[r][k4];
            float hs[4][4];
            #pragma unroll
            for (int r = 0; r < 4; r++) {
                hs[r][0] = hv[r].x; hs[r][1] = hv[r].y; hs[r][2] = hv[r].z; hs[r][3] = hv[r].w;
            }
            #pragma unroll
            for (int u = 0; u < 4; u++) {
                float4 w4 = *(const float4*)(wl2 + (k4 * 4 + u) * OUT_D);
                float w[4] = {w4.x, w4.y, w4.z, w4.w};
                #pragma unroll
                for (int r = 0; r < 4; r++) {
                    float h = hs[r][u];
                    #pragma unroll
                    for (int c = 0; c < 4; c++) a2[r][c] = fmaf(h, w[c], a2[r][c]);
                }
            }
        }
        float bl[4];
        #pragma unroll
        for (int c = 0; c < 4; c++) bl[c] = __ldg(blin + cg2 * 4 + c);
        #pragma unroll
        for (int r = 0; r < 4; r++) {
            int row = rowBase + rg2 * 4 + r;
            if (rg2 * 4 + r < nValid) {
                float* op = linOut + (size_t)row * OUT_D + cg2 * 4;
                *(float4*)op = make_float4(a2[r][0] + bl[0], a2[r][1] + bl[1],
                                           a2[r][2] + bl[2], a2[r][3] + bl[3]);
            }
        }
    }
}

// ---------------------------------------------------------------------------
// Host launcher
// ---------------------------------------------------------------------------
extern "C" void kernel_launch(void* const* d_in, const int* in_sizes, int n_in,
                              void* d_out, int out_size)
{
    const float* x_user    = (const float*)d_in[0];
    const float* x_movie   = (const float*)d_in[1];
    const int*   edge_user = (const int*)d_in[2];
    const int*   edge_movie= (const int*)d_in[3];
    const float* W1l = (const float*)d_in[4];
    const float* W1r = (const float*)d_in[5];
    const float* b1  = (const float*)d_in[6];
    const float* W2l = (const float*)d_in[7];
    const float* W2r = (const float*)d_in[8];
    const float* b2  = (const float*)d_in[9];
    const float* W3l = (const float*)d_in[10];
    const float* W3r = (const float*)d_in[11];
    const float* b3  = (const float*)d_in[12];
    const float* Wlin1 = (const float*)d_in[13];
    const float* blin1 = (const float*)d_in[14];
    const float* Wlin2 = (const float*)d_in[15];
    const float* blin2 = (const float*)d_in[16];

    float* out = (float*)d_out;
    float* out_user  = out;
    float* out_movie = out + (size_t)N_USER * OUT_D;

    float* scratch = nullptr;
    cudaGetSymbolAddress((void**)&scratch, g_scratch);
    float* agg1   = scratch + OFF_AGG1;
    float* agg2   = scratch + OFF_AGG2;
    float* agg3   = scratch + OFF_AGG3;
    float* degU   = scratch + OFF_DEGU;
    float* degM   = scratch + OFF_DEGM;
    float* userx  = scratch + OFF_USERX;
    float* moviex = scratch + OFF_MOVIEX;

    // dynamic smem (bytes), TM=64:
    const int SM_K64   = (2*64*HID  + 64*2*64) * 4;                 // 98304  (96KB)
    const int SM_K64F  = (2*64*HID  + 64*2*64  + HID*OUT_D) * 4;    // 131072 (128KB)
    const int SM_K128F = (2*128*HID + 64*2*128 + HID*OUT_D) * 4;    // 229376 (224KB)

    cudaFuncSetAttribute(update_kernel<64, false, true>,
                         cudaFuncAttributeMaxDynamicSharedMemorySize, SM_K64);
    cudaFuncSetAttribute(update_kernel<64, true, true>,
                         cudaFuncAttributeMaxDynamicSharedMemorySize, SM_K64F);
    cudaFuncSetAttribute(update_kernel<128, true, false>,
                         cudaFuncAttributeMaxDynamicSharedMemorySize, SM_K128F);

    cudaMemsetAsync(scratch, 0, (size_t)ZERO_FLOATS * sizeof(float), 0);

    // fused conv1+conv2 scatter + degree counters
    scatter12_kernel<<<(NE * 16) / 256, 256>>>(
        (const float4*)x_movie, (const float4*)x_user,
        edge_movie, edge_user, agg1, agg2, degU, degM);

    const int GU = (N_USER  + 63) / 64;   // 1563
    const int GM = (N_MOVIE + 63) / 64;   // 313

    // conv2 update (movie): moviex + fused out_movie
    update_kernel<64, true, true><<<GM, 256, SM_K64F>>>(
        agg2, degM, x_movie, W2l, W2r, b2, Wlin2, blin2, moviex, out_movie, N_MOVIE);

    // conv1 update (user): userx
    update_kernel<64, false, true><<<GU, 256, SM_K64>>>(
        agg1, degU, x_user, W1l, W1r, b1, nullptr, nullptr, userx, nullptr, N_USER);

    // conv3 scatter: moviex -> agg3
    scatter3_kernel<<<(NE * 32) / 256, 256>>>(
        (const float4*)moviex, edge_movie, edge_user, agg3);

    // conv3 update (user) + fused lin1: out_user
    update_kernel<128, true, false><<<GU, 256, SM_K128F>>>(
        agg3, degU, userx, W3l, W3r, b3, Wlin1, blin1, nullptr, out_user, N_USER);
}